// round 1
// baseline (speedup 1.0000x reference)
#include <cuda_runtime.h>
#include <math.h>

#define NN 100000
#define EE 1600000
#define FIN 128
#define HD  64
#define CC  40
#define LL  6

// ---------------- scratch (static device allocation; no cudaMalloc) ----------------
__device__ int   g_deg[NN];
__device__ int   g_rowptr[NN + 1];
__device__ int   g_fill[NN];
__device__ float g_dis[NN];
__device__ int   g_colidx[EE];
__device__ float g_hn[(size_t)NN * HD];   // dis-scaled pre-aggregation features
__device__ float g_h [(size_t)NN * HD];   // post-relu layer output (next layer input)
__device__ float g_jk[(size_t)NN * HD];   // running JumpingKnowledge max

// ---------------- graph preprocessing ----------------
__global__ void k_zero_deg() {
    int i = blockIdx.x * blockDim.x + threadIdx.x;
    if (i < NN) g_deg[i] = 0;
}

__global__ void k_count(const int* __restrict__ dst) {
    int e = blockIdx.x * blockDim.x + threadIdx.x;
    if (e < EE) atomicAdd(&g_deg[dst[e]], 1);
}

// Single-block exclusive scan: thread-sequential segments + block scan of 1024 partials.
__global__ void k_scan() {
    __shared__ int sh[1024];
    int tid = threadIdx.x;
    const int SEG = (NN + 1023) / 1024;   // 98
    int beg = tid * SEG;
    int end = min(beg + SEG, NN);
    int s = 0;
    for (int i = beg; i < end; i++) s += g_deg[i];
    sh[tid] = s;
    __syncthreads();
    for (int off = 1; off < 1024; off <<= 1) {
        int t = (tid >= off) ? sh[tid - off] : 0;
        __syncthreads();
        sh[tid] += t;
        __syncthreads();
    }
    int run = sh[tid] - s;                 // exclusive prefix for this segment
    for (int i = beg; i < end; i++) { g_rowptr[i] = run; run += g_deg[i]; }
    if (tid == 1023) g_rowptr[NN] = sh[1023];   // == EE
}

__global__ void k_init() {
    int i = blockIdx.x * blockDim.x + threadIdx.x;
    if (i < NN) {
        g_fill[i] = g_rowptr[i];
        g_dis[i] = rsqrtf((float)(g_deg[i] + 1));   // +1: self loop
    }
}

__global__ void k_scatter(const int* __restrict__ src, const int* __restrict__ dst) {
    int e = blockIdx.x * blockDim.x + threadIdx.x;
    if (e < EE) {
        int p = atomicAdd(&g_fill[dst[e]], 1);
        g_colidx[p] = src[e];
    }
}

// ---------------- GEMM:  hn[row,:] = dis[row] * (A[row,:] @ W)  ----------------
// 64x64 output tile, K staged in 64-wide chunks, 4x4 microtile per thread (256 thr).
template<int K, bool FROMX>
__global__ void k_gemm(const float* __restrict__ Aext, const float* __restrict__ W) {
    __shared__ float As[64][68];
    __shared__ float Bs[64][68];
    const float* __restrict__ A = FROMX ? Aext : (const float*)g_h;
    int tid = threadIdx.x;
    int tx = tid & 15, ty = tid >> 4;
    int brow = blockIdx.x * 64;
    float acc[4][4] = {};

    for (int kc = 0; kc < K; kc += 64) {
        // stage A (64 rows x 64 k) and W (64 k x 64 cols)
        int c4 = tx * 4;
        #pragma unroll
        for (int i = 0; i < 4; i++) {
            int r = ty + 16 * i;
            int row = brow + r;
            float4 v = make_float4(0.f, 0.f, 0.f, 0.f);
            if (row < NN) v = *(const float4*)&A[(size_t)row * K + kc + c4];
            *(float4*)&As[r][c4] = v;
        }
        #pragma unroll
        for (int i = 0; i < 4; i++) {
            int kr = ty + 16 * i;
            *(float4*)&Bs[kr][c4] = *(const float4*)&W[(size_t)(kc + kr) * HD + c4];
        }
        __syncthreads();

        #pragma unroll
        for (int k = 0; k < 64; k++) {
            float a0 = As[ty * 4 + 0][k];
            float a1 = As[ty * 4 + 1][k];
            float a2 = As[ty * 4 + 2][k];
            float a3 = As[ty * 4 + 3][k];
            float4 b = *(float4*)&Bs[k][tx * 4];
            acc[0][0] += a0 * b.x; acc[0][1] += a0 * b.y; acc[0][2] += a0 * b.z; acc[0][3] += a0 * b.w;
            acc[1][0] += a1 * b.x; acc[1][1] += a1 * b.y; acc[1][2] += a1 * b.z; acc[1][3] += a1 * b.w;
            acc[2][0] += a2 * b.x; acc[2][1] += a2 * b.y; acc[2][2] += a2 * b.z; acc[2][3] += a2 * b.w;
            acc[3][0] += a3 * b.x; acc[3][1] += a3 * b.y; acc[3][2] += a3 * b.z; acc[3][3] += a3 * b.w;
        }
        __syncthreads();
    }

    #pragma unroll
    for (int i = 0; i < 4; i++) {
        int row = brow + ty * 4 + i;
        if (row < NN) {
            float d = g_dis[row];
            float4 o = make_float4(acc[i][0] * d, acc[i][1] * d, acc[i][2] * d, acc[i][3] * d);
            *(float4*)&g_hn[(size_t)row * HD + tx * 4] = o;
        }
    }
}

// ---------------- aggregation: warp per node, CSR pull + self term ----------------
// h[v,:] = relu(dis[v]*(hn[v,:] + sum_{u->v} hn[u,:]) + b);  jk = max(jk, h)
__global__ void k_agg(const float* __restrict__ bias, int first) {
    int warp = (blockIdx.x * blockDim.x + threadIdx.x) >> 5;
    int lane = threadIdx.x & 31;
    if (warp >= NN) return;
    int v = warp;
    int beg = g_rowptr[v], end = g_rowptr[v + 1];

    size_t fo = (size_t)v * HD + lane * 2;
    float2 acc = *(const float2*)&g_hn[fo];   // self-loop term

    int p = beg;
    for (; p + 4 <= end; p += 4) {
        int u0 = g_colidx[p + 0];
        int u1 = g_colidx[p + 1];
        int u2 = g_colidx[p + 2];
        int u3 = g_colidx[p + 3];
        float2 t0 = *(const float2*)&g_hn[(size_t)u0 * HD + lane * 2];
        float2 t1 = *(const float2*)&g_hn[(size_t)u1 * HD + lane * 2];
        float2 t2 = *(const float2*)&g_hn[(size_t)u2 * HD + lane * 2];
        float2 t3 = *(const float2*)&g_hn[(size_t)u3 * HD + lane * 2];
        acc.x += (t0.x + t1.x) + (t2.x + t3.x);
        acc.y += (t0.y + t1.y) + (t2.y + t3.y);
    }
    for (; p < end; p++) {
        int u = g_colidx[p];
        float2 t = *(const float2*)&g_hn[(size_t)u * HD + lane * 2];
        acc.x += t.x; acc.y += t.y;
    }

    float d = g_dis[v];
    float2 b = *(const float2*)&bias[lane * 2];
    float hx = fmaxf(fmaf(d, acc.x, b.x), 0.f);
    float hy = fmaxf(fmaf(d, acc.y, b.y), 0.f);
    *(float2*)&g_h[fo] = make_float2(hx, hy);
    if (first) {
        *(float2*)&g_jk[fo] = make_float2(hx, hy);
    } else {
        float2 j = *(const float2*)&g_jk[fo];
        *(float2*)&g_jk[fo] = make_float2(fmaxf(j.x, hx), fmaxf(j.y, hy));
    }
}

// ---------------- head: warp per row, jk @ fc_w + fc_b, log_softmax ----------------
__global__ void k_proj(const float* __restrict__ fcw, const float* __restrict__ fcb,
                       float* __restrict__ out) {
    __shared__ float Wsm[HD * CC];
    __shared__ float bsm[CC];
    int tid = threadIdx.x;
    for (int i = tid; i < HD * CC; i += blockDim.x) Wsm[i] = fcw[i];
    if (tid < CC) bsm[tid] = fcb[tid];
    __syncthreads();

    int warp = (blockIdx.x * blockDim.x + tid) >> 5;
    int lane = tid & 31;
    if (warp >= NN) return;
    int v = warp;

    float2 jv = *(const float2*)&g_jk[(size_t)v * HD + lane * 2];
    bool act = lane < 20;                   // 20 lanes x 2 cols = 40
    int c0 = lane * 2;
    float a0 = 0.f, a1 = 0.f;
    #pragma unroll
    for (int k = 0; k < HD; k++) {
        float hv = __shfl_sync(0xffffffffu, (k & 1) ? jv.y : jv.x, k >> 1);
        if (act) {
            float2 w = *(const float2*)&Wsm[k * CC + c0];
            a0 = fmaf(hv, w.x, a0);
            a1 = fmaf(hv, w.y, a1);
        }
    }
    if (act) { a0 += bsm[c0]; a1 += bsm[c0 + 1]; }

    float m = act ? fmaxf(a0, a1) : -INFINITY;
    #pragma unroll
    for (int off = 16; off; off >>= 1) m = fmaxf(m, __shfl_xor_sync(0xffffffffu, m, off));
    float s = act ? (expf(a0 - m) + expf(a1 - m)) : 0.f;
    #pragma unroll
    for (int off = 16; off; off >>= 1) s += __shfl_xor_sync(0xffffffffu, s, off);
    float lse = m + logf(s);

    if (act) {
        float2 o = make_float2(a0 - lse, a1 - lse);
        *(float2*)&out[(size_t)v * CC + c0] = o;
    }
}

// ---------------- launch ----------------
extern "C" void kernel_launch(void* const* d_in, const int* in_sizes, int n_in,
                              void* d_out, int out_size) {
    const float* x   = (const float*)d_in[0];
    const int*   ei  = (const int*)  d_in[1];
    const float* W0  = (const float*)d_in[2];
    const float* Ws  = (const float*)d_in[3];
    const float* bs  = (const float*)d_in[4];
    const float* fcw = (const float*)d_in[5];
    const float* fcb = (const float*)d_in[6];
    float* out = (float*)d_out;

    const int* src = ei;         // edge_index[0]
    const int* dst = ei + EE;    // edge_index[1]

    // CSR build (once per call, reused by all 6 layers)
    k_zero_deg<<<(NN + 255) / 256, 256>>>();
    k_count   <<<(EE + 255) / 256, 256>>>(dst);
    k_scan    <<<1, 1024>>>();
    k_init    <<<(NN + 255) / 256, 256>>>();
    k_scatter <<<(EE + 255) / 256, 256>>>(src, dst);

    const int GEMM_GRID = (NN + 63) / 64;
    const int AGG_GRID  = (NN + 7) / 8;     // 8 warps per 256-thread block

    // layer 0: x (N x 128) @ W0
    k_gemm<FIN, true><<<GEMM_GRID, 256>>>(x, W0);
    k_agg<<<AGG_GRID, 256>>>(bs + 0 * HD, 1);

    // layers 1..5: h (N x 64) @ Ws[l-1]
    for (int l = 1; l < LL; l++) {
        k_gemm<HD, false><<<GEMM_GRID, 256>>>(nullptr, Ws + (size_t)(l - 1) * HD * HD);
        k_agg<<<AGG_GRID, 256>>>(bs + (size_t)l * HD, 0);
    }

    // head
    k_proj<<<AGG_GRID, 256>>>(fcw, fcb, out);
}